// round 1
// baseline (speedup 1.0000x reference)
#include <cuda_runtime.h>
#include <cuda_bf16.h>
#include <cstdint>

// Problem constants (fixed by the dataset)
#define NE 8
#define NH 1024
#define NI 2048
#define NT 1024
#define NPAIR (NT * 2)      // 2048 (token, expert) pairs, always exactly 2 per token
#define N1 (2 * NI)         // 4096

// ---------------------------------------------------------------------------
// Scratch (device globals — no allocation allowed in kernel_launch)
// ---------------------------------------------------------------------------
__device__ int g_cnt[NE];
__device__ int g_off[NE];
__device__ int g_pair_token[NPAIR];
__device__ int g_pair_expert[NPAIR];
__device__ int g_tok_pair[NT * 2];
__device__ int g_tok_e[NT * 2];
__device__ float g_tok_w[NT * 2];

__device__ __nv_bfloat16 g_Ahi[NPAIR * NH];     // gathered x, bf16 high part
__device__ __nv_bfloat16 g_Alo[NPAIR * NH];     // residual
__device__ float g_h[(size_t)NPAIR * N1];       // GEMM1 output (pre-activation)
__device__ __nv_bfloat16 g_acthi[NPAIR * NI];
__device__ __nv_bfloat16 g_actlo[NPAIR * NI];
__device__ float g_y[(size_t)NPAIR * NH];       // GEMM2 output

// ---------------------------------------------------------------------------
// Kernel 1: router — softmax/top-2 + per-expert compaction, one block
// ---------------------------------------------------------------------------
__global__ void router_kernel(const float* __restrict__ logits) {
    __shared__ int s_cnt[NE];
    __shared__ int s_cur[NE];
    int t = threadIdx.x;
    if (t < NE) s_cnt[t] = 0;
    __syncthreads();

    float l[NE];
#pragma unroll
    for (int e = 0; e < NE; e++) l[e] = logits[t * NE + e];

    int e0 = 0;
#pragma unroll
    for (int e = 1; e < NE; e++) if (l[e] > l[e0]) e0 = e;
    int e1 = (e0 == 0) ? 1 : 0;
#pragma unroll
    for (int e = 0; e < NE; e++) if (e != e0 && l[e] > l[e1]) e1 = e;

    // renormalized top-2 softmax == softmax over the two selected logits
    float w0 = 1.0f / (1.0f + expf(l[e1] - l[e0]));
    float w1 = 1.0f - w0;

    atomicAdd(&s_cnt[e0], 1);
    atomicAdd(&s_cnt[e1], 1);
    __syncthreads();

    if (t == 0) {
        int o = 0;
        for (int e = 0; e < NE; e++) {
            g_off[e] = o;
            s_cur[e] = o;
            g_cnt[e] = s_cnt[e];
            o += s_cnt[e];
        }
    }
    __syncthreads();

    int p0 = atomicAdd(&s_cur[e0], 1);
    int p1 = atomicAdd(&s_cur[e1], 1);
    g_pair_token[p0] = t;  g_pair_expert[p0] = e0;
    g_pair_token[p1] = t;  g_pair_expert[p1] = e1;
    g_tok_pair[2 * t] = p0;      g_tok_pair[2 * t + 1] = p1;
    g_tok_e[2 * t] = e0;         g_tok_e[2 * t + 1] = e1;
    g_tok_w[2 * t] = w0;         g_tok_w[2 * t + 1] = w1;
}

// ---------------------------------------------------------------------------
// Kernel 2: gather x rows into compacted bf16 hi/lo A matrix
// ---------------------------------------------------------------------------
__global__ void gather_kernel(const float* __restrict__ x) {
    int p = blockIdx.x;
    int t = g_pair_token[p];
    float4 v = reinterpret_cast<const float4*>(x + (size_t)t * NH)[threadIdx.x];
    int base = p * NH + threadIdx.x * 4;
    float f[4] = {v.x, v.y, v.z, v.w};
#pragma unroll
    for (int j = 0; j < 4; j++) {
        __nv_bfloat16 hi = __float2bfloat16(f[j]);
        g_Ahi[base + j] = hi;
        g_Alo[base + j] = __float2bfloat16(f[j] - __bfloat162float(hi));
    }
}

// ---------------------------------------------------------------------------
// GEMM: C[M_e, N] = (Ahi+Alo)[M_e, K] @ B[e][N, K]^T   (split-bf16, fp32 acc)
// mma.sync.m16n8k16 bf16; weights converted fp32->bf16 (exact for MXFP4) on
// the SMEM store path.
// ---------------------------------------------------------------------------
#define BM 128
#define BN 64
#define BK 32
#define BKP 40   // padded K stride (halfs) — conflict-free frag loads

__device__ __forceinline__ void mma16816(float* c, const uint32_t* a, const uint32_t* b) {
    asm volatile(
        "mma.sync.aligned.m16n8k16.row.col.f32.bf16.bf16.f32 "
        "{%0,%1,%2,%3}, {%4,%5,%6,%7}, {%8,%9}, {%0,%1,%2,%3};\n"
        : "+f"(c[0]), "+f"(c[1]), "+f"(c[2]), "+f"(c[3])
        : "r"(a[0]), "r"(a[1]), "r"(a[2]), "r"(a[3]), "r"(b[0]), "r"(b[1]));
}

// PASS 1: A = g_Ahi/g_Alo (K=NH), B = w13, C = g_h (N=N1)
// PASS 2: A = g_acthi/g_actlo (K=NI), B = w2, C = g_y (N=NH)
template <int N, int K, int PASS>
__global__ __launch_bounds__(256) void gemm_split_kernel(const float* __restrict__ Bw) {
    const __nv_bfloat16* __restrict__ Ahi = (PASS == 1) ? g_Ahi : g_acthi;
    const __nv_bfloat16* __restrict__ Alo = (PASS == 1) ? g_Alo : g_actlo;
    float* __restrict__ C = (PASS == 1) ? g_h : g_y;

    const int e = blockIdx.z;
    const int cntE = g_cnt[e];
    const int m0 = blockIdx.y * BM;
    if (m0 >= cntE) return;
    const int offE = g_off[e];
    const int n0 = blockIdx.x * BN;
    const float* __restrict__ Bp = Bw + ((size_t)e * N + n0) * K;

    __shared__ __nv_bfloat16 As_hi[BM * BKP];
    __shared__ __nv_bfloat16 As_lo[BM * BKP];
    __shared__ __nv_bfloat16 Bs[BN * BKP];

    const int tid = threadIdx.x;
    const int lane = tid & 31;
    const int warp = tid >> 5;
    const int wm = warp >> 1;   // 4 warps along M
    const int wn = warp & 1;    // 2 warps along N

    float acc[2][4][4];
#pragma unroll
    for (int a = 0; a < 2; a++)
#pragma unroll
        for (int b = 0; b < 4; b++)
#pragma unroll
            for (int c = 0; c < 4; c++) acc[a][b][c] = 0.0f;

    for (int k0 = 0; k0 < K; k0 += BK) {
        __syncthreads();
        // --- A tile loads: 128 rows x 32 halfs, vectorized 8-half chunks ---
#pragma unroll
        for (int it = 0; it < 2; it++) {
            int q = tid + it * 256;
            int r = q >> 2;
            int kv = (q & 3) * 8;
            uint4 vhi = make_uint4(0, 0, 0, 0);
            uint4 vlo = make_uint4(0, 0, 0, 0);
            if (m0 + r < cntE) {
                size_t gidx = (size_t)(offE + m0 + r) * K + k0 + kv;
                vhi = *reinterpret_cast<const uint4*>(Ahi + gidx);
                vlo = *reinterpret_cast<const uint4*>(Alo + gidx);
            }
            *reinterpret_cast<uint4*>(&As_hi[r * BKP + kv]) = vhi;
            *reinterpret_cast<uint4*>(&As_lo[r * BKP + kv]) = vlo;
        }
        // --- B tile loads: 64 rows x 32 fp32 -> bf16 (exact for MXFP4 w) ---
#pragma unroll
        for (int it = 0; it < 2; it++) {
            int q = tid + it * 256;
            int n = q >> 3;
            int kv = (q & 7) * 4;
            float4 v = *reinterpret_cast<const float4*>(Bp + (size_t)n * K + k0 + kv);
            __nv_bfloat16* d = &Bs[n * BKP + kv];
            d[0] = __float2bfloat16(v.x);
            d[1] = __float2bfloat16(v.y);
            d[2] = __float2bfloat16(v.z);
            d[3] = __float2bfloat16(v.w);
        }
        __syncthreads();

#pragma unroll
        for (int kk = 0; kk < BK; kk += 16) {
            uint32_t a_hi[2][4], a_lo[2][4], bf[4][2];
            const int c0 = kk + (lane & 3) * 2;
#pragma unroll
            for (int mi = 0; mi < 2; mi++) {
                int r0 = (wm * 32 + mi * 16 + (lane >> 2)) * BKP;
                a_hi[mi][0] = *reinterpret_cast<const uint32_t*>(&As_hi[r0 + c0]);
                a_hi[mi][1] = *reinterpret_cast<const uint32_t*>(&As_hi[r0 + 8 * BKP + c0]);
                a_hi[mi][2] = *reinterpret_cast<const uint32_t*>(&As_hi[r0 + c0 + 8]);
                a_hi[mi][3] = *reinterpret_cast<const uint32_t*>(&As_hi[r0 + 8 * BKP + c0 + 8]);
                a_lo[mi][0] = *reinterpret_cast<const uint32_t*>(&As_lo[r0 + c0]);
                a_lo[mi][1] = *reinterpret_cast<const uint32_t*>(&As_lo[r0 + 8 * BKP + c0]);
                a_lo[mi][2] = *reinterpret_cast<const uint32_t*>(&As_lo[r0 + c0 + 8]);
                a_lo[mi][3] = *reinterpret_cast<const uint32_t*>(&As_lo[r0 + 8 * BKP + c0 + 8]);
            }
#pragma unroll
            for (int ni = 0; ni < 4; ni++) {
                int nb = (wn * 32 + ni * 8 + (lane >> 2)) * BKP;
                bf[ni][0] = *reinterpret_cast<const uint32_t*>(&Bs[nb + c0]);
                bf[ni][1] = *reinterpret_cast<const uint32_t*>(&Bs[nb + c0 + 8]);
            }
#pragma unroll
            for (int mi = 0; mi < 2; mi++)
#pragma unroll
                for (int ni = 0; ni < 4; ni++) {
                    mma16816(acc[mi][ni], a_hi[mi], bf[ni]);
                    mma16816(acc[mi][ni], a_lo[mi], bf[ni]);
                }
        }
    }

    // --- epilogue ---
#pragma unroll
    for (int mi = 0; mi < 2; mi++) {
        int r = wm * 32 + mi * 16 + (lane >> 2);
#pragma unroll
        for (int ni = 0; ni < 4; ni++) {
            int n = n0 + wn * 32 + ni * 8 + (lane & 3) * 2;
            if (m0 + r < cntE) {
                float* cp = C + (size_t)(offE + m0 + r) * N + n;
                cp[0] = acc[mi][ni][0];
                cp[1] = acc[mi][ni][1];
            }
            if (m0 + r + 8 < cntE) {
                float* cp = C + (size_t)(offE + m0 + r + 8) * N + n;
                cp[0] = acc[mi][ni][2];
                cp[1] = acc[mi][ni][3];
            }
        }
    }
}

// ---------------------------------------------------------------------------
// Kernel 4: swiglu activation, fp32 -> bf16 hi/lo
// ---------------------------------------------------------------------------
__global__ void act_kernel(const float* __restrict__ w13_bias) {
    int idx = blockIdx.x * blockDim.x + threadIdx.x;   // NPAIR * NI total
    int p = idx >> 11;
    int i = idx & (NI - 1);
    int e = g_pair_expert[p];
    float glu = g_h[(size_t)p * N1 + i] + w13_bias[e * N1 + i];
    float lin = g_h[(size_t)p * N1 + NI + i] + w13_bias[e * N1 + NI + i];
    float s = 1.0f / (1.0f + expf(-1.702f * glu));
    float a = glu * s * (lin + 1.0f);
    __nv_bfloat16 hi = __float2bfloat16(a);
    g_acthi[p * NI + i] = hi;
    g_actlo[p * NI + i] = __float2bfloat16(a - __bfloat162float(hi));
}

// ---------------------------------------------------------------------------
// Kernel 6: gated combine (+ expert bias); writes every output element
// ---------------------------------------------------------------------------
__global__ void combine_kernel(const float* __restrict__ w2_bias, float* __restrict__ out) {
    int t = blockIdx.x;
    int p0 = g_tok_pair[2 * t], p1 = g_tok_pair[2 * t + 1];
    int e0 = g_tok_e[2 * t], e1 = g_tok_e[2 * t + 1];
    float w0 = g_tok_w[2 * t], w1 = g_tok_w[2 * t + 1];
    int hv = threadIdx.x;   // 256 threads x float4 = 1024
    float4 y0 = reinterpret_cast<const float4*>(g_y + (size_t)p0 * NH)[hv];
    float4 y1 = reinterpret_cast<const float4*>(g_y + (size_t)p1 * NH)[hv];
    float4 b0 = reinterpret_cast<const float4*>(w2_bias + e0 * NH)[hv];
    float4 b1 = reinterpret_cast<const float4*>(w2_bias + e1 * NH)[hv];
    float4 o;
    o.x = w0 * (y0.x + b0.x) + w1 * (y1.x + b1.x);
    o.y = w0 * (y0.y + b0.y) + w1 * (y1.y + b1.y);
    o.z = w0 * (y0.z + b0.z) + w1 * (y1.z + b1.z);
    o.w = w0 * (y0.w + b0.w) + w1 * (y1.w + b1.w);
    reinterpret_cast<float4*>(out + (size_t)t * NH)[hv] = o;
}

// ---------------------------------------------------------------------------
// Launch
// ---------------------------------------------------------------------------
extern "C" void kernel_launch(void* const* d_in, const int* in_sizes, int n_in,
                              void* d_out, int out_size) {
    const float* x      = (const float*)d_in[0];
    const float* logits = (const float*)d_in[1];
    const float* w13    = (const float*)d_in[2];
    const float* w2     = (const float*)d_in[3];
    const float* b13    = (const float*)d_in[4];
    const float* b2     = (const float*)d_in[5];
    float* out = (float*)d_out;

    router_kernel<<<1, NT>>>(logits);
    gather_kernel<<<NPAIR, 256>>>(x);
    gemm_split_kernel<N1, NH, 1><<<dim3(N1 / BN, NT / BM, NE), 256>>>(w13);
    act_kernel<<<(NPAIR * NI) / 256, 256>>>(b13);
    gemm_split_kernel<NH, NI, 2><<<dim3(NH / BN, NT / BM, NE), 256>>>(w2);
    combine_kernel<<<NT, 256>>>(b2, out);
}